// round 4
// baseline (speedup 1.0000x reference)
#include <cuda_runtime.h>

// CritiGraph_64175401337324 — two-kernel split, v3 fixed:
//   A: streaming eu = cos(sta_emb, nei_emb), DRAM-bound (~8 us, at roofline)
//   B: integer cos-sim loss / argmin / selection, issue-bound (restructured)

namespace {
constexpr int T_   = 1024;
constexpr int S_   = 64;
constexpr int D_   = 256;
constexpr int TP_  = 8;
constexpr int C_   = 65;
constexpr int CUR_TP_ = 4;
}

__device__ int   g_is64;
__device__ float g_eu[T_ * S_];          // 256 KB static scratch

// pack |v| with sign in bit 31
__device__ __forceinline__ unsigned enc_loc(int v) {
    unsigned a = (unsigned)(v < 0 ? -v : v);
    if (v < 0) a |= 0x80000000u;
    return a;
}

// sign * (16 - e), e = frexp-exponent of ((|a|^|b|)+1). Exact in fp32.
__device__ __forceinline__ float cos_core(unsigned ea, unsigned eb) {
    unsigned u = ea ^ eb;
    int e = 32 - __clz((int)((u & 0x7FFFFFFFu) + 1u));
    float f = (float)(16 - e);
    return (u & 0x80000000u) ? -f : f;
}

// ---------------------------------------------------------------------------
// Kernel A: eu[t][s] = dot(sta,nei) / (||sta|| * ||nei||)
// ---------------------------------------------------------------------------
__global__ void __launch_bounds__(128, 1) eu_kernel(
    const float* __restrict__ sta_emb,
    const float* __restrict__ nei_emb,
    const void*  __restrict__ sta_loc_probe)
{
    if (blockIdx.x == 0 && threadIdx.x == 0) {
        // int64 values in [-131071,131071] => high half == sign-ext of low half
        const long long* p = (const long long*)sta_loc_probe;
        int ok = 1;
        for (int i = 0; i < 64; ++i) {
            long long v = p[i];
            int lo = (int)v, hi = (int)(v >> 32);
            if (hi != (lo < 0 ? -1 : 0)) { ok = 0; break; }
        }
        g_is64 = ok;
    }

    const int t    = blockIdx.x >> 2;
    const int quad = blockIdx.x & 3;
    const int tid  = threadIdx.x;
    const int lane = tid & 31;
    const int warp = tid >> 5;

    __shared__ __align__(16) float s_sta[D_];
    __shared__ float s_red[4];
    __shared__ float s_sq;

    float x0 = sta_emb[t * D_ + tid];
    float x1 = sta_emb[t * D_ + 128 + tid];
    s_sta[tid]       = x0;
    s_sta[tid + 128] = x1;
    float p2 = x0 * x0 + x1 * x1;
    #pragma unroll
    for (int off = 16; off; off >>= 1) p2 += __shfl_xor_sync(0xFFFFFFFFu, p2, off);
    if (lane == 0) s_red[warp] = p2;
    __syncthreads();
    if (tid == 0) s_sq = sqrtf(s_red[0] + s_red[1] + s_red[2] + s_red[3]);
    __syncthreads();

    const float sqss = s_sq;
    const float4* st4 = (const float4*)s_sta;
    const float4 ua = st4[lane];
    const float4 ub = st4[lane + 32];

    const int sbase = quad * 16 + warp * 4;
    const float4* base = (const float4*)(nei_emb + ((size_t)(t * S_ + sbase)) * D_);

    float4 a[4], b[4];
    #pragma unroll
    for (int r = 0; r < 4; ++r) {
        a[r] = base[r * 64 + lane];
        b[r] = base[r * 64 + lane + 32];
    }

    float dot[4], nn[4];
    #pragma unroll
    for (int r = 0; r < 4; ++r) {
        dot[r] = a[r].x*ua.x + a[r].y*ua.y + a[r].z*ua.z + a[r].w*ua.w
               + b[r].x*ub.x + b[r].y*ub.y + b[r].z*ub.z + b[r].w*ub.w;
        nn[r]  = a[r].x*a[r].x + a[r].y*a[r].y + a[r].z*a[r].z + a[r].w*a[r].w
               + b[r].x*b[r].x + b[r].y*b[r].y + b[r].z*b[r].z + b[r].w*b[r].w;
    }
    #pragma unroll
    for (int off = 16; off; off >>= 1) {
        #pragma unroll
        for (int r = 0; r < 4; ++r) {
            dot[r] += __shfl_xor_sync(0xFFFFFFFFu, dot[r], off);
            nn[r]  += __shfl_xor_sync(0xFFFFFFFFu, nn[r],  off);
        }
    }
    if (lane == 0) {
        #pragma unroll
        for (int r = 0; r < 4; ++r)
            g_eu[t * S_ + sbase + r] = dot[r] / (sqss * sqrtf(nn[r]));
    }
}

// ---------------------------------------------------------------------------
// Kernel B: one CTA per t, 256 threads, fully prefetched + parallel argmin.
// ---------------------------------------------------------------------------
__global__ void __launch_bounds__(256, 5) loss_kernel(
    const void*  __restrict__ sta_loc,
    const void*  __restrict__ nei_loc,
    const void*  __restrict__ rand_numbers,
    const float* __restrict__ mask,
    const float* __restrict__ rand_vals,
    const float* __restrict__ t_rand,
    float* __restrict__ out)
{
    const int t    = blockIdx.x;
    const int tid  = threadIdx.x;
    const int lane = tid & 31;
    const int warp = tid >> 5;
    const int is64 = g_is64;

    __shared__ __align__(16) float    s_eu[S_];
    __shared__ __align__(16) float    s_w[S_];          // |eu|*mask*invlth
    __shared__ float    s_cs[S_][TP_];                  // cos_sn
    __shared__ __align__(16) unsigned s_nlT[TP_][68];   // transposed, padded
    __shared__ __align__(16) float    s_BT[TP_][68];    // (sum-cs)/8 - eu
    __shared__ int      s_clv[C_ * TP_];
    __shared__ float    s_loss[C_ * TP_];
    __shared__ float    s_p32[4][TP_];                  // candidate-32 partials
    __shared__ float    s_rv[TP_], s_rl[TP_];
    __shared__ float    s_red[2];
    __shared__ float    s_invlth;
    __shared__ int      s_ori[TP_];
    __shared__ int      s_sel;

    // ---- prefetch burst (all globals, high MLP) ----
    int nl0, nl1, rn;
    if (is64) {
        const long long* NL = (const long long*)nei_loc + (size_t)t * (S_ * TP_);
        nl0 = (int)NL[tid];
        nl1 = (int)NL[tid + 256];
        rn  = (int)((const long long*)rand_numbers)[t * 256 + tid];
    } else {
        const int* NL = (const int*)nei_loc + t * (S_ * TP_);
        nl0 = NL[tid];
        nl1 = NL[tid + 256];
        rn  = ((const int*)rand_numbers)[t * 256 + tid];
    }
    float m = 0.f, eu = 0.f;
    if (tid < S_) {
        m  = mask[t * S_ + tid];
        eu = g_eu[t * S_ + tid];
        s_eu[tid] = eu;
    }
    if (tid < TP_) {
        s_ori[tid] = is64 ? (int)((const long long*)sta_loc)[t * TP_ + tid]
                          : ((const int*)sta_loc)[t * TP_ + tid];
        s_rv[tid]  = rand_vals[t * TP_ + tid];
    }
    if (tid == 0) s_sel = (t_rand[t] < 0.8f) ? 1 : 0;

    // lth partial reduce (warps 0-1; mask is 0/1 so any order exact)
    if (tid < S_) {
        float l = m;
        #pragma unroll
        for (int off = 16; off; off >>= 1) l += __shfl_xor_sync(0xFFFFFFFFu, l, off);
        if (lane == 0) s_red[warp] = l;
    }
    __syncthreads();                       // s_ori, s_red, s_eu ready

    if (tid == 0) s_invlth = 1.0f / (s_red[0] + s_red[1] + 1e-12f);

    // cos_sn + nei encodings (2 items/thread)
    {
        const int s = tid >> 3, p = tid & 7;
        const unsigned op = enc_loc(s_ori[p]);
        unsigned ne0 = enc_loc(nl0);
        unsigned ne1 = enc_loc(nl1);
        s_nlT[p][s]      = ne0;
        s_nlT[p][s + 32] = ne1;
        s_cs[s][p]       = cos_core(op, ne0) * 0.0625f;   // exact (true cos)
        s_cs[s + 32][p]  = cos_core(op, ne1) * 0.0625f;
    }

    // connection candidates (value kept in register for phase 4)
    int vcand;
    {
        const int j = tid >> 3, p = tid & 7;
        const int h = j >> 1;
        vcand = (s_ori[p] ^ (1 << h)) ^ (rn & ((1 << h) - 1));
        s_clv[j * TP_ + p]        = vcand;
        s_clv[(j + 33) * TP_ + p] = -vcand;
    }
    if (tid < TP_) s_clv[32 * TP_ + tid] = s_ori[tid];
    __syncthreads();                       // cs complete, invlth ready

    // B[p][s] = (sum-cs)/8 - eu ; w' = |eu|*m*invlth
    {
        const int s = tid >> 3, p = tid & 7;
        float sum0 = 0.f, sum1 = 0.f;
        #pragma unroll
        for (int pp = 0; pp < TP_; ++pp) { sum0 += s_cs[s][pp]; sum1 += s_cs[s + 32][pp]; }
        s_BT[p][s]      = (sum0 - s_cs[s][p])      * 0.125f - s_eu[s];
        s_BT[p][s + 32] = (sum1 - s_cs[s + 32][p]) * 0.125f - s_eu[s + 32];
    }
    if (tid < S_) s_w[tid] = fabsf(eu) * m * s_invlth;
    __syncthreads();

    // ---- phase 4: candidate pair (j, j+33) per thread, 13 inst / 2 cand / s
    {
        const int p = tid & 7, j = tid >> 3;
        const unsigned e0 = enc_loc(vcand);
        const unsigned flipmask = e0 ? 0x80000000u : 0u;   // -res sign flip (except res==0)

        const uint4*  neP = (const uint4*) &s_nlT[p][0];
        const float4* bP  = (const float4*)&s_BT[p][0];
        const float4* wP  = (const float4*)s_w;

        float acc0 = 0.f, acc1 = 0.f;

#define PROC(NE, B, W) do {                                                   \
        unsigned u  = e0 ^ (NE);                                              \
        unsigned x2 = u * 2u + 2u;            /* = 2*((u&0x7fffffff)+1) */    \
        float cf = (float)__clz((int)x2);                                     \
        float mg = __fmaf_rn(cf, 0.0078125f, -0.1171875f);  /* (clz-15)/128 */\
        float v0 = __uint_as_float(__float_as_uint(mg) ^ (u & 0x80000000u));  \
        float v1 = __uint_as_float(__float_as_uint(v0) ^ flipmask);           \
        float d0 = __fadd_rn((B), v0);                                        \
        float d1 = __fadd_rn((B), v1);                                        \
        acc0 = __fmaf_rn(d0, __fmul_rn(d0, (W)), acc0);                       \
        acc1 = __fmaf_rn(d1, __fmul_rn(d1, (W)), acc1);                       \
    } while (0)

        #pragma unroll 4
        for (int g = 0; g < 16; ++g) {
            uint4  n4 = neP[g];
            float4 B4 = bP[g];
            float4 W4 = wP[g];
            PROC(n4.x, B4.x, W4.x);
            PROC(n4.y, B4.y, W4.y);
            PROC(n4.z, B4.z, W4.z);
            PROC(n4.w, B4.w, W4.w);
        }
#undef PROC

        s_loss[j * TP_ + p]        = acc0;
        s_loss[(j + 33) * TP_ + p] = acc1;
    }
    // candidate 32 (= ori): ct-eu = B + cos_sn/8 = fma(cs, 0.125, B)
    if (warp == 7) {
        const int p = lane & 7, chunk = lane >> 3;
        const int sb = chunk * 16;
        float acc = 0.f;
        #pragma unroll
        for (int s = sb; s < sb + 16; ++s) {
            float d = __fmaf_rn(s_cs[s][p], 0.125f, s_BT[p][s]);
            acc = __fmaf_rn(d, __fmul_rn(d, s_w[s]), acc);
        }
        s_p32[chunk][p] = acc;
    }
    __syncthreads();

    // ---- phase 5: warp p does argmin over 65 via lexicographic shuffle-min
    {
        const int p = warp;
        float va = s_loss[lane * TP_ + p];            // c = lane
        float vb = s_loss[(lane + 33) * TP_ + p];     // c = lane+33
        float v = va; int ci = lane;
        if (vb < v) { v = vb; ci = lane + 33; }       // tie keeps lower idx
        if (lane == 0) {
            float v32 = ((s_p32[0][p] + s_p32[1][p]) + s_p32[2][p]) + s_p32[3][p];
            s_loss[32 * TP_ + p] = v32;
            if (v32 < v || (v32 == v && 32 < ci)) { v = v32; ci = 32; }
        }
        #pragma unroll
        for (int off = 16; off; off >>= 1) {
            float v2 = __shfl_xor_sync(0xFFFFFFFFu, v, off);
            int   c2 = __shfl_xor_sync(0xFFFFFFFFu, ci, off);
            if (v2 < v || (v2 == v && c2 < ci)) { v = v2; ci = c2; }
        }
        if (lane == 0) {
            float rp = s_rv[p];
            int rank = 0;
            #pragma unroll
            for (int q = 0; q < TP_; ++q)
                rank += (s_rv[q] < rp) || (s_rv[q] == rp && q < p);
            int idx = (rank < CUR_TP_ && s_sel) ? ci : 32;
            out[t * TP_ + p] = (float)s_clv[idx * TP_ + p];
            s_rl[p] = s_loss[idx * TP_ + p];
        }
    }
    __syncthreads();
    if (tid == 0) {
        float rl = 0.f;
        #pragma unroll
        for (int p = 0; p < TP_; ++p) rl = __fadd_rn(rl, s_rl[p]);
        out[T_ * TP_ + t] = rl * 0.125f;
    }
}

extern "C" void kernel_launch(void* const* d_in, const int* in_sizes, int n_in,
                              void* d_out, int out_size) {
    (void)in_sizes; (void)n_in; (void)out_size;
    eu_kernel<<<T_ * 4, 128>>>(
        (const float*)d_in[3], (const float*)d_in[4], d_in[0]);
    loss_kernel<<<T_, 256>>>(
        d_in[0], d_in[1], d_in[2],
        (const float*)d_in[5], (const float*)d_in[6], (const float*)d_in[7],
        (float*)d_out);
}

// round 5
// speedup vs baseline: 1.5492x; 1.5492x over previous
#include <cuda_runtime.h>

// CritiGraph_64175401337324 — fused single kernel (one CTA per t):
// eu = cos(sta_emb, nei_emb) streamed per-CTA (overlaps with integer work),
// then integer cos-sim loss / argmin / selection (validated R4 code).

namespace {
constexpr int T_   = 1024;
constexpr int S_   = 64;
constexpr int D_   = 256;
constexpr int TP_  = 8;
constexpr int C_   = 65;
constexpr int CUR_TP_ = 4;
}

__device__ int g_is64;

__global__ void detect_dtype_kernel(const void* p0) {
    // int64 values in [-131071,131071] => high half == sign-ext of low half
    const long long* p = (const long long*)p0;
    int ok = 1;
    for (int i = 0; i < 64; ++i) {
        long long v = p[i];
        int lo = (int)v, hi = (int)(v >> 32);
        if (hi != (lo < 0 ? -1 : 0)) { ok = 0; break; }
    }
    g_is64 = ok;
}

// pack |v| with sign in bit 31
__device__ __forceinline__ unsigned enc_loc(int v) {
    unsigned a = (unsigned)(v < 0 ? -v : v);
    if (v < 0) a |= 0x80000000u;
    return a;
}

// sign * (16 - e), e = frexp-exponent of ((|a|^|b|)+1). Exact in fp32.
__device__ __forceinline__ float cos_core(unsigned ea, unsigned eb) {
    unsigned u = ea ^ eb;
    int e = 32 - __clz((int)((u & 0x7FFFFFFFu) + 1u));
    float f = (float)(16 - e);
    return (u & 0x80000000u) ? -f : f;
}

__global__ void __launch_bounds__(256) fused_kernel(
    const void*  __restrict__ sta_loc,
    const void*  __restrict__ nei_loc,
    const void*  __restrict__ rand_numbers,
    const float* __restrict__ sta_emb,
    const float* __restrict__ nei_emb,
    const float* __restrict__ mask,
    const float* __restrict__ rand_vals,
    const float* __restrict__ t_rand,
    float* __restrict__ out)
{
    const int t    = blockIdx.x;
    const int tid  = threadIdx.x;
    const int lane = tid & 31;
    const int warp = tid >> 5;
    const int is64 = g_is64;

    __shared__ __align__(16) float    s_eu[S_];
    __shared__ __align__(16) float    s_w[S_];          // |eu|*mask*invlth
    __shared__ float    s_cs[S_][TP_];                  // cos_sn
    __shared__ __align__(16) unsigned s_nlT[TP_][68];   // transposed, padded
    __shared__ __align__(16) float    s_BT[TP_][68];    // (sum-cs)/8 - eu
    __shared__ int      s_clv[C_ * TP_];
    __shared__ float    s_loss[C_ * TP_];
    __shared__ float    s_p32[4][TP_];                  // candidate-32 partials
    __shared__ float    s_rv[TP_], s_rl[TP_];
    __shared__ float    s_red[2];
    __shared__ float    s_invlth;
    __shared__ int      s_ori[TP_];
    __shared__ int      s_sel;

    // ---- integer/small prefetch burst ----
    int nl0, nl1, rn;
    if (is64) {
        const long long* NL = (const long long*)nei_loc + (size_t)t * (S_ * TP_);
        nl0 = (int)NL[tid];
        nl1 = (int)NL[tid + 256];
        rn  = (int)((const long long*)rand_numbers)[t * 256 + tid];
    } else {
        const int* NL = (const int*)nei_loc + t * (S_ * TP_);
        nl0 = NL[tid];
        nl1 = NL[tid + 256];
        rn  = ((const int*)rand_numbers)[t * 256 + tid];
    }
    float m = 0.f;
    if (tid < S_)  m = mask[t * S_ + tid];
    if (tid < TP_) {
        s_ori[tid] = is64 ? (int)((const long long*)sta_loc)[t * TP_ + tid]
                          : ((const int*)sta_loc)[t * TP_ + tid];
        s_rv[tid]  = rand_vals[t * TP_ + tid];
    }
    if (tid == 0) s_sel = (t_rand[t] < 0.8f) ? 1 : 0;

    // ---- eu: warp owns 8 nei rows; no cross-warp dependency, no barrier ----
    {
        const float4* st4 = (const float4*)(sta_emb + (size_t)t * D_);
        const float4  ua  = st4[lane];
        const float4  ub  = st4[lane + 32];
        const float4* nb  = (const float4*)(nei_emb + ((size_t)(t * S_ + warp * 8)) * D_);

        float dot[8], nn[8];
        #pragma unroll
        for (int b = 0; b < 2; ++b) {
            float4 A[4], Bv[4];
            #pragma unroll
            for (int r = 0; r < 4; ++r) {
                A[r]  = nb[(b * 4 + r) * 64 + lane];
                Bv[r] = nb[(b * 4 + r) * 64 + lane + 32];
            }
            #pragma unroll
            for (int r = 0; r < 4; ++r) {
                int k = b * 4 + r;
                dot[k] = A[r].x*ua.x + A[r].y*ua.y + A[r].z*ua.z + A[r].w*ua.w
                       + Bv[r].x*ub.x + Bv[r].y*ub.y + Bv[r].z*ub.z + Bv[r].w*ub.w;
                nn[k]  = A[r].x*A[r].x + A[r].y*A[r].y + A[r].z*A[r].z + A[r].w*A[r].w
                       + Bv[r].x*Bv[r].x + Bv[r].y*Bv[r].y + Bv[r].z*Bv[r].z + Bv[r].w*Bv[r].w;
            }
        }
        float ss = ua.x*ua.x + ua.y*ua.y + ua.z*ua.z + ua.w*ua.w
                 + ub.x*ub.x + ub.y*ub.y + ub.z*ub.z + ub.w*ub.w;
        #pragma unroll
        for (int off = 16; off; off >>= 1) {
            ss += __shfl_xor_sync(0xFFFFFFFFu, ss, off);
            #pragma unroll
            for (int k = 0; k < 8; ++k) {
                dot[k] += __shfl_xor_sync(0xFFFFFFFFu, dot[k], off);
                nn[k]  += __shfl_xor_sync(0xFFFFFFFFu, nn[k],  off);
            }
        }
        if (lane < 8)
            s_eu[warp * 8 + lane] = dot[lane] / (sqrtf(ss) * sqrtf(nn[lane]));
    }

    // lth partial reduce (warps 0-1; mask is 0/1 so any order exact)
    if (tid < S_) {
        float l = m;
        #pragma unroll
        for (int off = 16; off; off >>= 1) l += __shfl_xor_sync(0xFFFFFFFFu, l, off);
        if (lane == 0) s_red[warp] = l;
    }
    __syncthreads();                       // s_ori, s_red, s_eu ready

    if (tid == 0) s_invlth = 1.0f / (s_red[0] + s_red[1] + 1e-12f);

    // cos_sn + nei encodings (2 items/thread)
    {
        const int s = tid >> 3, p = tid & 7;
        const unsigned op = enc_loc(s_ori[p]);
        unsigned ne0 = enc_loc(nl0);
        unsigned ne1 = enc_loc(nl1);
        s_nlT[p][s]      = ne0;
        s_nlT[p][s + 32] = ne1;
        s_cs[s][p]       = cos_core(op, ne0) * 0.0625f;   // exact
        s_cs[s + 32][p]  = cos_core(op, ne1) * 0.0625f;
    }

    // connection candidates (value kept in register for phase 4)
    int vcand;
    {
        const int j = tid >> 3, p = tid & 7;
        const int h = j >> 1;
        vcand = (s_ori[p] ^ (1 << h)) ^ (rn & ((1 << h) - 1));
        s_clv[j * TP_ + p]        = vcand;
        s_clv[(j + 33) * TP_ + p] = -vcand;
    }
    if (tid < TP_) s_clv[32 * TP_ + tid] = s_ori[tid];
    __syncthreads();                       // cs complete, invlth ready

    // B[p][s] = (sum-cs)/8 - eu ; w' = |eu|*m*invlth
    {
        const int s = tid >> 3, p = tid & 7;
        float sum0 = 0.f, sum1 = 0.f;
        #pragma unroll
        for (int pp = 0; pp < TP_; ++pp) { sum0 += s_cs[s][pp]; sum1 += s_cs[s + 32][pp]; }
        s_BT[p][s]      = (sum0 - s_cs[s][p])      * 0.125f - s_eu[s];
        s_BT[p][s + 32] = (sum1 - s_cs[s + 32][p]) * 0.125f - s_eu[s + 32];
    }
    if (tid < S_) s_w[tid] = fabsf(s_eu[tid]) * m * s_invlth;
    __syncthreads();

    // ---- phase 4: candidate pair (j, j+33) per thread
    {
        const int p = tid & 7, j = tid >> 3;
        const unsigned e0 = enc_loc(vcand);
        const unsigned flipmask = e0 ? 0x80000000u : 0u;   // -res sign flip (except res==0)

        const uint4*  neP = (const uint4*) &s_nlT[p][0];
        const float4* bP  = (const float4*)&s_BT[p][0];
        const float4* wP  = (const float4*)s_w;

        float acc0 = 0.f, acc1 = 0.f;

#define PROC(NE, B, W) do {                                                   \
        unsigned u  = e0 ^ (NE);                                              \
        unsigned x2 = u * 2u + 2u;            /* = 2*((u&0x7fffffff)+1) */    \
        float cf = (float)__clz((int)x2);                                     \
        float mg = __fmaf_rn(cf, 0.0078125f, -0.1171875f);  /* (clz-15)/128 */\
        float v0 = __uint_as_float(__float_as_uint(mg) ^ (u & 0x80000000u));  \
        float v1 = __uint_as_float(__float_as_uint(v0) ^ flipmask);           \
        float d0 = __fadd_rn((B), v0);                                        \
        float d1 = __fadd_rn((B), v1);                                        \
        acc0 = __fmaf_rn(d0, __fmul_rn(d0, (W)), acc0);                       \
        acc1 = __fmaf_rn(d1, __fmul_rn(d1, (W)), acc1);                       \
    } while (0)

        #pragma unroll 4
        for (int g = 0; g < 16; ++g) {
            uint4  n4 = neP[g];
            float4 B4 = bP[g];
            float4 W4 = wP[g];
            PROC(n4.x, B4.x, W4.x);
            PROC(n4.y, B4.y, W4.y);
            PROC(n4.z, B4.z, W4.z);
            PROC(n4.w, B4.w, W4.w);
        }
#undef PROC

        s_loss[j * TP_ + p]        = acc0;
        s_loss[(j + 33) * TP_ + p] = acc1;
    }
    // candidate 32 (= ori): ct-eu = B + cos_sn/8 = fma(cs, 0.125, B)
    if (warp == 7) {
        const int p = lane & 7, chunk = lane >> 3;
        const int sb = chunk * 16;
        float acc = 0.f;
        #pragma unroll
        for (int s = sb; s < sb + 16; ++s) {
            float d = __fmaf_rn(s_cs[s][p], 0.125f, s_BT[p][s]);
            acc = __fmaf_rn(d, __fmul_rn(d, s_w[s]), acc);
        }
        s_p32[chunk][p] = acc;
    }
    __syncthreads();

    // ---- phase 5: warp p does argmin over 65 via lexicographic shuffle-min
    {
        const int p = warp;
        float va = s_loss[lane * TP_ + p];            // c = lane
        float vb = s_loss[(lane + 33) * TP_ + p];     // c = lane+33
        float v = va; int ci = lane;
        if (vb < v) { v = vb; ci = lane + 33; }       // tie keeps lower idx
        if (lane == 0) {
            float v32 = ((s_p32[0][p] + s_p32[1][p]) + s_p32[2][p]) + s_p32[3][p];
            s_loss[32 * TP_ + p] = v32;
            if (v32 < v || (v32 == v && 32 < ci)) { v = v32; ci = 32; }
        }
        #pragma unroll
        for (int off = 16; off; off >>= 1) {
            float v2 = __shfl_xor_sync(0xFFFFFFFFu, v, off);
            int   c2 = __shfl_xor_sync(0xFFFFFFFFu, ci, off);
            if (v2 < v || (v2 == v && c2 < ci)) { v = v2; ci = c2; }
        }
        if (lane == 0) {
            float rp = s_rv[p];
            int rank = 0;
            #pragma unroll
            for (int q = 0; q < TP_; ++q)
                rank += (s_rv[q] < rp) || (s_rv[q] == rp && q < p);
            int idx = (rank < CUR_TP_ && s_sel) ? ci : 32;
            out[t * TP_ + p] = (float)s_clv[idx * TP_ + p];
            s_rl[p] = s_loss[idx * TP_ + p];
        }
    }
    __syncthreads();
    if (tid == 0) {
        float rl = 0.f;
        #pragma unroll
        for (int p = 0; p < TP_; ++p) rl = __fadd_rn(rl, s_rl[p]);
        out[T_ * TP_ + t] = rl * 0.125f;
    }
}

extern "C" void kernel_launch(void* const* d_in, const int* in_sizes, int n_in,
                              void* d_out, int out_size) {
    (void)in_sizes; (void)n_in; (void)out_size;
    detect_dtype_kernel<<<1, 1>>>(d_in[0]);
    fused_kernel<<<T_, 256>>>(
        d_in[0], d_in[1], d_in[2],
        (const float*)d_in[3], (const float*)d_in[4], (const float*)d_in[5],
        (const float*)d_in[6], (const float*)d_in[7],
        (float*)d_out);
}

// round 6
// speedup vs baseline: 1.6685x; 1.0770x over previous
#include <cuda_runtime.h>

// CritiGraph_64175401337324 — fused kernel v2:
//  - loss factored as WB2 + Σ(2wB)v + Σw v²  (candidate-independent WB2)
//  - merged-butterfly warp reduction (31 vs 85 shuffles, same FP tree)
//  - 5 CTAs/SM, integer work overlapped under nei_emb load latency

namespace {
constexpr int T_   = 1024;
constexpr int S_   = 64;
constexpr int D_   = 256;
constexpr int TP_  = 8;
constexpr int C_   = 65;
constexpr int CUR_TP_ = 4;
}

__device__ int g_is64;

__global__ void detect_dtype_kernel(const void* p0) {
    // int64 values in [-131071,131071] => high half == sign-ext of low half
    const long long* p = (const long long*)p0;
    int ok = 1;
    for (int i = 0; i < 64; ++i) {
        long long v = p[i];
        int lo = (int)v, hi = (int)(v >> 32);
        if (hi != (lo < 0 ? -1 : 0)) { ok = 0; break; }
    }
    g_is64 = ok;
}

// pack |v| with sign in bit 31
__device__ __forceinline__ unsigned enc_loc(int v) {
    unsigned a = (unsigned)(v < 0 ? -v : v);
    if (v < 0) a |= 0x80000000u;
    return a;
}

// sign * (16 - e), e = frexp-exponent of ((|a|^|b|)+1). Exact in fp32.
__device__ __forceinline__ float cos_core(unsigned ea, unsigned eb) {
    unsigned u = ea ^ eb;
    int e = 32 - __clz((int)((u & 0x7FFFFFFFu) + 1u));
    float f = (float)(16 - e);
    return (u & 0x80000000u) ? -f : f;
}

__global__ void __launch_bounds__(256, 5) fused_kernel(
    const void*  __restrict__ sta_loc,
    const void*  __restrict__ nei_loc,
    const void*  __restrict__ rand_numbers,
    const float* __restrict__ sta_emb,
    const float* __restrict__ nei_emb,
    const float* __restrict__ mask,
    const float* __restrict__ rand_vals,
    const float* __restrict__ t_rand,
    float* __restrict__ out)
{
    const int t    = blockIdx.x;
    const int tid  = threadIdx.x;
    const int lane = tid & 31;
    const int warp = tid >> 5;
    const int is64 = g_is64;

    __shared__ __align__(16) float    s_eu[S_];
    __shared__ __align__(16) float    s_w[S_];          // |eu|*mask*invlth
    __shared__ __align__(16) float    s_m[S_];
    __shared__ __align__(16) float    s_csT[TP_][68];   // cos_sn, transposed
    __shared__ __align__(16) unsigned s_nlT[TP_][68];   // enc(nei), transposed
    __shared__ __align__(16) float    s_G[TP_][68];     // 2*w*B
    __shared__ float    s_WB2[TP_];                     // sum w*B^2
    __shared__ int      s_clv[C_ * TP_];
    __shared__ float    s_loss[C_ * TP_];
    __shared__ float    s_p32[4][TP_];
    __shared__ float    s_rv[TP_], s_rl[TP_];
    __shared__ float    s_red[2];
    __shared__ int      s_sel;

    // ---- issue nei batch-1 loads first (in flight during integer work) ----
    const float4* st4 = (const float4*)(sta_emb + (size_t)t * D_);
    const float4  ua  = st4[lane];
    const float4  ub  = st4[lane + 32];
    const float4* nb  = (const float4*)(nei_emb + ((size_t)(t * S_ + warp * 8)) * D_);

    float4 A[4], Bv[4];
    #pragma unroll
    for (int r = 0; r < 4; ++r) {
        A[r]  = nb[r * 64 + lane];
        Bv[r] = nb[r * 64 + lane + 32];
    }

    // ---- integer loads + encode (overlapped with nei latency) ----
    const int p_ = tid & 7;
    const int j_ = tid >> 3;
    int nl0, nl1, rn, orip;
    if (is64) {
        const long long* NL = (const long long*)nei_loc + (size_t)t * (S_ * TP_);
        nl0  = (int)NL[tid];
        nl1  = (int)NL[tid + 256];
        rn   = (int)((const long long*)rand_numbers)[t * 256 + tid];
        orip = (int)((const long long*)sta_loc)[t * TP_ + p_];
    } else {
        const int* NL = (const int*)nei_loc + t * (S_ * TP_);
        nl0  = NL[tid];
        nl1  = NL[tid + 256];
        rn   = ((const int*)rand_numbers)[t * 256 + tid];
        orip = ((const int*)sta_loc)[t * TP_ + p_];
    }
    float m = 0.f;
    if (tid < S_) { m = mask[t * S_ + tid]; s_m[tid] = m; }
    if (tid < TP_) {
        s_rv[tid] = rand_vals[t * TP_ + tid];
        s_clv[32 * TP_ + tid] = orip;     // p_ == tid here
    }
    if (tid == 0) s_sel = (t_rand[t] < 0.8f) ? 1 : 0;

    {   // encodings + cos_sn (exact multiples of 1/16)
        const unsigned op = enc_loc(orip);
        unsigned ne0 = enc_loc(nl0);
        unsigned ne1 = enc_loc(nl1);
        s_nlT[p_][j_]      = ne0;
        s_nlT[p_][j_ + 32] = ne1;
        s_csT[p_][j_]      = cos_core(op, ne0) * 0.0625f;
        s_csT[p_][j_ + 32] = cos_core(op, ne1) * 0.0625f;
    }
    int vcand;
    {
        const int h = j_ >> 1;
        vcand = (orip ^ (1 << h)) ^ (rn & ((1 << h) - 1));
        s_clv[j_ * TP_ + p_]        = vcand;
        s_clv[(j_ + 33) * TP_ + p_] = -vcand;
    }
    // lth partial reduce (mask is 0/1: exact in any order)
    if (tid < S_) {
        float l = m;
        #pragma unroll
        for (int off = 16; off; off >>= 1) l += __shfl_xor_sync(0xFFFFFFFFu, l, off);
        if (lane == 0) s_red[warp] = l;
    }

    // ---- eu: FFMA batch-1, load batch-2, FFMA batch-2 ----
    float dot[8], nn[8];
    #pragma unroll
    for (int r = 0; r < 4; ++r) {
        dot[r] = A[r].x*ua.x + A[r].y*ua.y + A[r].z*ua.z + A[r].w*ua.w
               + Bv[r].x*ub.x + Bv[r].y*ub.y + Bv[r].z*ub.z + Bv[r].w*ub.w;
        nn[r]  = A[r].x*A[r].x + A[r].y*A[r].y + A[r].z*A[r].z + A[r].w*A[r].w
               + Bv[r].x*Bv[r].x + Bv[r].y*Bv[r].y + Bv[r].z*Bv[r].z + Bv[r].w*Bv[r].w;
    }
    #pragma unroll
    for (int r = 0; r < 4; ++r) {
        A[r]  = nb[(4 + r) * 64 + lane];
        Bv[r] = nb[(4 + r) * 64 + lane + 32];
    }
    #pragma unroll
    for (int r = 0; r < 4; ++r) {
        dot[4+r] = A[r].x*ua.x + A[r].y*ua.y + A[r].z*ua.z + A[r].w*ua.w
                 + Bv[r].x*ub.x + Bv[r].y*ub.y + Bv[r].z*ub.z + Bv[r].w*ub.w;
        nn[4+r]  = A[r].x*A[r].x + A[r].y*A[r].y + A[r].z*A[r].z + A[r].w*A[r].w
                 + Bv[r].x*Bv[r].x + Bv[r].y*Bv[r].y + Bv[r].z*Bv[r].z + Bv[r].w*Bv[r].w;
    }
    float ss = ua.x*ua.x + ua.y*ua.y + ua.z*ua.z + ua.w*ua.w
             + ub.x*ub.x + ub.y*ub.y + ub.z*ub.z + ub.w*ub.w;

    // ---- merged butterfly: 16 values reduced in 31 shuffles (same FP tree) ----
    {
        float r16[16];
        #pragma unroll
        for (int i = 0; i < 8; ++i) { r16[i] = dot[i]; r16[8+i] = nn[i]; }
        float t0[16];
        #pragma unroll
        for (int i = 0; i < 16; ++i)
            t0[i] = r16[i] + __shfl_xor_sync(0xFFFFFFFFu, r16[i], 16);
        float m8[8];
        #pragma unroll
        for (int k = 0; k < 8; ++k) m8[k] = (lane & 16) ? t0[k+8] : t0[k];
        float u4[8];
        #pragma unroll
        for (int k = 0; k < 8; ++k)
            u4[k] = m8[k] + __shfl_xor_sync(0xFFFFFFFFu, m8[k], 8);
        float q[4];
        #pragma unroll
        for (int k = 0; k < 4; ++k) q[k] = (lane & 8) ? u4[k+4] : u4[k];
        float v4[4];
        #pragma unroll
        for (int k = 0; k < 4; ++k)
            v4[k] = q[k] + __shfl_xor_sync(0xFFFFFFFFu, q[k], 4);
        float w0 = (lane & 4) ? v4[2] : v4[0];
        float w1 = (lane & 4) ? v4[3] : v4[1];
        float x0 = w0 + __shfl_xor_sync(0xFFFFFFFFu, w0, 2);
        float x1 = w1 + __shfl_xor_sync(0xFFFFFFFFu, w1, 2);
        float y  = (lane & 2) ? x1 : x0;
        float z  = y + __shfl_xor_sync(0xFFFFFFFFu, y, 1);
        #pragma unroll
        for (int off = 16; off; off >>= 1) ss += __shfl_xor_sync(0xFFFFFFFFu, ss, off);
        float nnv = __shfl_xor_sync(0xFFFFFFFFu, z, 16);   // nn for same row
        if (lane < 16 && !(lane & 1)) {
            int row = lane >> 1;                            // row = (lane>>1)&7
            s_eu[warp * 8 + row] = z / (sqrtf(ss) * sqrtf(nnv));
        }
    }
    __syncthreads();                     // s_eu, s_red, s_csT, s_nlT, s_m ready

    // ---- B-phase: warp = p, lanes cover s and s+32 ----
    {
        const float invlth = __frcp_rn(s_red[0] + s_red[1] + 1e-12f);
        const int p = warp, s0 = lane, s1 = lane + 32;
        float sum0 = 0.f, sum1 = 0.f;
        #pragma unroll
        for (int pp = 0; pp < TP_; ++pp) { sum0 += s_csT[pp][s0]; sum1 += s_csT[pp][s1]; }
        float cs0 = s_csT[p][s0], cs1 = s_csT[p][s1];
        float eu0 = s_eu[s0],     eu1 = s_eu[s1];
        float B0 = (sum0 - cs0) * 0.125f - eu0;            // exact A8, 1 rounding
        float B1 = (sum1 - cs1) * 0.125f - eu1;
        float w0 = fabsf(eu0) * s_m[s0] * invlth;
        float w1 = fabsf(eu1) * s_m[s1] * invlth;
        float q0 = w0 * B0, q1 = w1 * B1;
        s_G[p][s0] = q0 + q0;                              // 2wB (exact x2)
        s_G[p][s1] = q1 + q1;
        if (p == 0) { s_w[s0] = w0; s_w[s1] = w1; }
        float wb2 = __fmaf_rn(q1, B1, q0 * B0);
        #pragma unroll
        for (int off = 16; off; off >>= 1) wb2 += __shfl_xor_sync(0xFFFFFFFFu, wb2, off);
        if (lane == 0) s_WB2[p] = wb2;
    }
    __syncthreads();

    // ---- phase 4: pair (j, j+33); t2 shared, t1 sign-flips exactly ----
    {
        const int p = p_, j = j_;
        const unsigned e0 = enc_loc(vcand);
        const unsigned flip = e0 ? 0x80000000u : 0u;

        const uint4*  neP = (const uint4*) &s_nlT[p][0];
        const float4* GP  = (const float4*)&s_G[p][0];
        const float4* wP  = (const float4*)s_w;

        float t1 = 0.f, t2 = 0.f;

#define PROC(NE, G, W) do {                                                   \
        unsigned u  = e0 ^ (NE);                                              \
        unsigned x2 = u * 2u + 2u;                                            \
        float cf = (float)__clz((int)x2);                                     \
        float mg = __fmaf_rn(cf, 0.0078125f, -0.1171875f);                    \
        float sG = __uint_as_float(__float_as_uint(G) ^ (u & 0x80000000u));   \
        t1 = __fmaf_rn(mg, sG, t1);                                           \
        t2 = __fmaf_rn(__fmul_rn(mg, mg), (W), t2);                           \
    } while (0)

        #pragma unroll 4
        for (int g = 0; g < 16; ++g) {
            uint4  n4 = neP[g];
            float4 G4 = GP[g];
            float4 W4 = wP[g];
            PROC(n4.x, G4.x, W4.x);
            PROC(n4.y, G4.y, W4.y);
            PROC(n4.z, G4.z, W4.z);
            PROC(n4.w, G4.w, W4.w);
        }
#undef PROC

        float base = s_WB2[p] + t2;
        s_loss[j * TP_ + p]        = base + t1;
        s_loss[(j + 33) * TP_ + p] = base + __uint_as_float(__float_as_uint(t1) ^ flip);
    }
    // candidate 32 (= ori): v = cos_sn/8, same factored form
    if (warp == 7) {
        const int p = lane & 7, chunk = lane >> 3;
        const int sb = chunk * 16;
        float t1 = 0.f, t2 = 0.f;
        #pragma unroll
        for (int s = sb; s < sb + 16; ++s) {
            float v = s_csT[p][s] * 0.125f;
            t1 = __fmaf_rn(v, s_G[p][s], t1);
            t2 = __fmaf_rn(__fmul_rn(v, v), s_w[s], t2);
        }
        s_p32[chunk][p] = t1 + t2;
    }
    __syncthreads();

    // ---- phase 5: warp p argmin over 65 (lexicographic shuffle-min) ----
    {
        const int p = warp;
        float va = s_loss[lane * TP_ + p];
        float vb = s_loss[(lane + 33) * TP_ + p];
        float v = va; int ci = lane;
        if (vb < v) { v = vb; ci = lane + 33; }
        if (lane == 0) {
            float v32 = s_WB2[p] +
                ((((s_p32[0][p] + s_p32[1][p]) + s_p32[2][p]) + s_p32[3][p]));
            s_loss[32 * TP_ + p] = v32;
            if (v32 < v || (v32 == v && 32 < ci)) { v = v32; ci = 32; }
        }
        #pragma unroll
        for (int off = 16; off; off >>= 1) {
            float v2 = __shfl_xor_sync(0xFFFFFFFFu, v, off);
            int   c2 = __shfl_xor_sync(0xFFFFFFFFu, ci, off);
            if (v2 < v || (v2 == v && c2 < ci)) { v = v2; ci = c2; }
        }
        if (lane == 0) {
            float rp = s_rv[p];
            int rank = 0;
            #pragma unroll
            for (int q = 0; q < TP_; ++q)
                rank += (s_rv[q] < rp) || (s_rv[q] == rp && q < p);
            int idx = (rank < CUR_TP_ && s_sel) ? ci : 32;
            out[t * TP_ + p] = (float)s_clv[idx * TP_ + p];
            s_rl[p] = s_loss[idx * TP_ + p];
        }
    }
    __syncthreads();
    if (tid == 0) {
        float rl = 0.f;
        #pragma unroll
        for (int p = 0; p < TP_; ++p) rl = __fadd_rn(rl, s_rl[p]);
        out[T_ * TP_ + t] = rl * 0.125f;
    }
}

extern "C" void kernel_launch(void* const* d_in, const int* in_sizes, int n_in,
                              void* d_out, int out_size) {
    (void)in_sizes; (void)n_in; (void)out_size;
    detect_dtype_kernel<<<1, 1>>>(d_in[0]);
    fused_kernel<<<T_, 256>>>(
        d_in[0], d_in[1], d_in[2],
        (const float*)d_in[3], (const float*)d_in[4], (const float*)d_in[5],
        (const float*)d_in[6], (const float*)d_in[7],
        (float*)d_out);
}